// round 4
// baseline (speedup 1.0000x reference)
#include <cuda_runtime.h>

#define HIDDEN 51
#define JP 64
#define KH 27            // k-rows per half; 54 rows: 0..50 = U, 51 = bias, 52 = W_w(x), 53 = pad
#define ROWS 56
#define L_SEQ 1000
#define NBLK 128
#define THREADS 512      // 4 groups x 128 threads; group = 2 batches

typedef unsigned long long ull;

// Gate-interleaved weights: g_U4[row*JP + j] = (i,f,g,o)
__device__ float4 g_U4[ROWS * JP];
__device__ float  g_L[JP];    // lin_w per j

// ---------- f32x2 helpers ----------
__device__ __forceinline__ ull pk2(float lo, float hi) {
    ull r; asm("mov.b64 %0, {%1, %2};" : "=l"(r) : "f"(lo), "f"(hi)); return r;
}
__device__ __forceinline__ void up2(float& lo, float& hi, ull v) {
    asm("mov.b64 {%0, %1}, %2;" : "=f"(lo), "=f"(hi) : "l"(v));
}
__device__ __forceinline__ ull f2fma(ull a, ull b, ull c) {
    ull d; asm("fma.rn.f32x2 %0, %1, %2, %3;" : "=l"(d) : "l"(a), "l"(b), "l"(c)); return d;
}
__device__ __forceinline__ ull f2add(ull a, ull b) {
    ull d; asm("add.rn.f32x2 %0, %1, %2;" : "=l"(d) : "l"(a), "l"(b)); return d;
}
// accurate fast tanh: 1 - 2/(exp(2x)+1); saturates correctly at +-inf
__device__ __forceinline__ float fast_tanh(float xv) {
    float e;
    asm("ex2.approx.f32 %0, %1;" : "=f"(e) : "f"(xv * 2.8853900817779268f));
    float r;
    asm("rcp.approx.f32 %0, %1;" : "=f"(r) : "f"(e + 1.0f));
    return fmaf(-2.0f, r, 1.0f);
}
__device__ __forceinline__ void group_bar(int barid) {
    asm volatile("bar.sync %0, %1;" :: "r"(barid), "r"(128) : "memory");
}

// ---------- prep ----------
__global__ void prep_kernel(const float* __restrict__ W_w, const float* __restrict__ W_b,
                            const float* __restrict__ U_w, const float* __restrict__ U_b,
                            const float* __restrict__ lin_w) {
    int i = blockIdx.x * 128 + threadIdx.x;   // 0 .. 3583 (56 rows x 64 j)
    if (i >= ROWS * JP) return;
    int k = i >> 6, j = i & 63;
    float4 u = make_float4(0.f, 0.f, 0.f, 0.f);
    if (j < HIDDEN) {
        if (k < HIDDEN) {
            u.x = U_w[(0 * HIDDEN + j) * HIDDEN + k];
            u.y = U_w[(1 * HIDDEN + j) * HIDDEN + k];
            u.z = U_w[(2 * HIDDEN + j) * HIDDEN + k];
            u.w = U_w[(3 * HIDDEN + j) * HIDDEN + k];
        } else if (k == HIDDEN) {             // bias row (h == 1)
            u.x = W_b[0 * HIDDEN + j] + U_b[0 * HIDDEN + j];
            u.y = W_b[1 * HIDDEN + j] + U_b[1 * HIDDEN + j];
            u.z = W_b[2 * HIDDEN + j] + U_b[2 * HIDDEN + j];
            u.w = W_b[3 * HIDDEN + j] + U_b[3 * HIDDEN + j];
        } else if (k == HIDDEN + 1) {         // x row (h == x_t)
            u.x = W_w[0 * HIDDEN + j];
            u.y = W_w[1 * HIDDEN + j];
            u.z = W_w[2 * HIDDEN + j];
            u.w = W_w[3 * HIDDEN + j];
        }
    }
    g_U4[i] = u;
    if (i < JP) g_L[i] = (i < HIDDEN) ? lin_w[i] : 0.f;
}

// ---------- main ----------
// 512 threads = 4 groups x 128. Group g: batches {blk*8+g*2, +1}.
// Within group: half = gtid>>6 (k rows half*27 .. half*27+26), j = gtid&63.
__global__ void __launch_bounds__(THREADS, 1)
lstm_main(const float* __restrict__ x, const float* __restrict__ lin_b,
          float* __restrict__ out) {
    // h stored DUPLICATED: h_shd[g][buf][row] = { (h,h) for b0, (h,h) for b1 } = 16B/row
    __shared__ __align__(16) ull    h_shd[4][2][ROWS][2];
    __shared__ __align__(16) float4 psum[4][2][2][JP];   // [group][half][batch][j] = (aif, ago)
    __shared__ float redp[4][4];                         // [group][warp-in-group]

    const int tid   = threadIdx.x;
    const int g     = tid >> 7;
    const int gtid  = tid & 127;
    const int half  = gtid >> 6;
    const int j     = gtid & 63;
    const int lane  = tid & 31;
    const int wgrp  = gtid >> 5;       // warp within group: 0,1 = batch0 j-halves; 2,3 = batch1
    const int myb   = half;            // phase-B batch owned by this thread
    const int b0    = blockIdx.x * 8 + g * 2;

    // Register-resident U rows (gate-packed pairs): rows half*27 .. half*27+26
    ull u_if[KH], u_go[KH];
#pragma unroll
    for (int kk = 0; kk < KH; kk++) {
        float4 u = g_U4[(half * KH + kk) * JP + j];
        u_if[kk] = pk2(u.x, u.y);
        u_go[kk] = pk2(u.z, u.w);
    }
    const float lw  = g_L[j];
    const float lbv = lin_b[0];

    // init h: zeros; row 51 = (1,1)
    for (int i = tid; i < 4 * 2 * ROWS * 2; i += THREADS) {
        int row = (i >> 1) % ROWS;
        ((ull*)h_shd)[i] = (row == HIDDEN) ? pk2(1.f, 1.f) : 0ULL;
    }
    __syncthreads();
    // row 52 of buf 0 = x_0 (one writer per (group, batch))
    float xn = 0.f;
    if (j == 62) {
        float x0 = x[(b0 + myb) * L_SEQ + 0];
        h_shd[g][0][HIDDEN + 1][myb] = pk2(x0, x0);
        xn = x[(b0 + myb) * L_SEQ + 1];
    }
    __syncthreads();

    float c = 0.f;   // cell state for (unit j, batch myb)

    for (int t = 0; t < L_SEQ; ++t) {
        const int rb = t & 1, wb = rb ^ 1;

        // ---- phase A: my k-half, both batches, zero-mov inner loop ----
        ull a_if0 = 0ULL, a_go0 = 0ULL, a_if1 = 0ULL, a_go1 = 0ULL;
        const ulonglong2* hr = (const ulonglong2*)&h_shd[g][rb][half * KH][0];
#pragma unroll
        for (int kk = 0; kk < KH; kk++) {
            ulonglong2 hp = hr[kk];              // LDS.128 broadcast: (h,h)b0, (h,h)b1
            a_if0 = f2fma(hp.x, u_if[kk], a_if0);
            a_go0 = f2fma(hp.x, u_go[kk], a_go0);
            a_if1 = f2fma(hp.y, u_if[kk], a_if1);
            a_go1 = f2fma(hp.y, u_go[kk], a_go1);
        }
        { ulonglong2 v; v.x = a_if0; v.y = a_go0; *(ulonglong2*)&psum[g][half][0][j] = v; }
        { ulonglong2 v; v.x = a_if1; v.y = a_go1; *(ulonglong2*)&psum[g][half][1][j] = v; }

        group_bar(g + 1);

        // ---- phase B: combine halves for (j, batch myb), update c/h ----
        ulonglong2 p0 = *(const ulonglong2*)&psum[g][0][myb][j];
        ulonglong2 p1 = *(const ulonglong2*)&psum[g][1][myb][j];
        ull s_if = f2add(p0.x, p1.x);
        ull s_go = f2add(p0.y, p1.y);
        float gi, gf, gg, go;
        up2(gi, gf, s_if);
        up2(gg, go, s_go);
        c = fmaf(gf, c, gi * gg);                // faithful: no sigmoids
        float h = go * fast_tanh(c);
        if (j < HIDDEN) h_shd[g][wb][j][myb] = pk2(h, h);
        if (j == 62) {                           // maintain x row for next step
            h_shd[g][wb][HIDDEN + 1][myb] = pk2(xn, xn);
            int tn = (t + 2 < L_SEQ) ? t + 2 : L_SEQ - 1;
            xn = x[(b0 + myb) * L_SEQ + tn];
        }

        float prod = h * lw;
        prod += __shfl_xor_sync(0xffffffffu, prod, 1);
        prod += __shfl_xor_sync(0xffffffffu, prod, 2);
        prod += __shfl_xor_sync(0xffffffffu, prod, 4);
        prod += __shfl_xor_sync(0xffffffffu, prod, 8);
        prod += __shfl_xor_sync(0xffffffffu, prod, 16);
        if (lane == 0) redp[g][wgrp] = prod;

        group_bar(g + 1);

        // ---- output for step t (overlaps next phase A) ----
        if (gtid < 2) {
            int b = gtid;
            out[(b0 + b) * L_SEQ + t] = redp[g][2 * b] + redp[g][2 * b + 1] + lbv;
        }
    }
}

extern "C" void kernel_launch(void* const* d_in, const int* in_sizes, int n_in,
                              void* d_out, int out_size) {
    (void)in_sizes; (void)n_in; (void)out_size;
    const float* x     = (const float*)d_in[0];
    const float* W_w   = (const float*)d_in[1];
    const float* W_b   = (const float*)d_in[2];
    const float* U_w   = (const float*)d_in[3];
    const float* U_b   = (const float*)d_in[4];
    const float* lin_w = (const float*)d_in[5];
    const float* lin_b = (const float*)d_in[6];
    // d_in[7] = future (static 0) — ignored.

    prep_kernel<<<28, 128>>>(W_w, W_b, U_w, U_b, lin_w);
    lstm_main<<<NBLK, THREADS>>>(x, lin_b, (float*)d_out);
}

// round 5
// speedup vs baseline: 1.4054x; 1.4054x over previous
#include <cuda_runtime.h>

#define HIDDEN 51
#define JP 64
#define KQ 13            // k-rows per quarter; 4*13 = 52 = rows 0..50 U + row 51 bias
#define KROWS 52
#define L_SEQ 1000
#define NBLK 128
#define THREADS 512      // 2 groups x 256; group = 4 batches, k split in 4 quarters

typedef unsigned long long ull;

// Gate-interleaved weights: g_U4[row*JP + j] = (i,f,g,o); row 51 = combined bias
__device__ float4 g_U4[KROWS * JP];
__device__ float4 g_W4[JP];   // x weights per j
__device__ float  g_L[JP];    // lin_w per j

// ---------- f32x2 helpers ----------
__device__ __forceinline__ ull pk2(float lo, float hi) {
    ull r; asm("mov.b64 %0, {%1, %2};" : "=l"(r) : "f"(lo), "f"(hi)); return r;
}
__device__ __forceinline__ void up2(float& lo, float& hi, ull v) {
    asm("mov.b64 {%0, %1}, %2;" : "=f"(lo), "=f"(hi) : "l"(v));
}
__device__ __forceinline__ ull f2fma(ull a, ull b, ull c) {
    ull d; asm("fma.rn.f32x2 %0, %1, %2, %3;" : "=l"(d) : "l"(a), "l"(b), "l"(c)); return d;
}
__device__ __forceinline__ ull f2add(ull a, ull b) {
    ull d; asm("add.rn.f32x2 %0, %1, %2;" : "=l"(d) : "l"(a), "l"(b)); return d;
}
// accurate fast tanh: 1 - 2/(exp(2x)+1); saturates correctly at +-inf
__device__ __forceinline__ float fast_tanh(float xv) {
    float e;
    asm("ex2.approx.f32 %0, %1;" : "=f"(e) : "f"(xv * 2.8853900817779268f));
    float r;
    asm("rcp.approx.f32 %0, %1;" : "=f"(r) : "f"(e + 1.0f));
    return fmaf(-2.0f, r, 1.0f);
}
__device__ __forceinline__ void group_bar(int barid) {
    asm volatile("bar.sync %0, %1;" :: "r"(barid), "r"(256) : "memory");
}

// ---------- prep ----------
__global__ void prep_kernel(const float* __restrict__ W_w, const float* __restrict__ W_b,
                            const float* __restrict__ U_w, const float* __restrict__ U_b,
                            const float* __restrict__ lin_w) {
    int i = blockIdx.x * 128 + threadIdx.x;   // 0 .. 3327 (52 rows x 64 j)
    if (i >= KROWS * JP) return;
    int k = i >> 6, j = i & 63;
    float4 u = make_float4(0.f, 0.f, 0.f, 0.f);
    if (j < HIDDEN) {
        if (k < HIDDEN) {
            u.x = U_w[(0 * HIDDEN + j) * HIDDEN + k];
            u.y = U_w[(1 * HIDDEN + j) * HIDDEN + k];
            u.z = U_w[(2 * HIDDEN + j) * HIDDEN + k];
            u.w = U_w[(3 * HIDDEN + j) * HIDDEN + k];
        } else {                              // row 51 = combined bias (h == 1)
            u.x = W_b[0 * HIDDEN + j] + U_b[0 * HIDDEN + j];
            u.y = W_b[1 * HIDDEN + j] + U_b[1 * HIDDEN + j];
            u.z = W_b[2 * HIDDEN + j] + U_b[2 * HIDDEN + j];
            u.w = W_b[3 * HIDDEN + j] + U_b[3 * HIDDEN + j];
        }
    }
    g_U4[i] = u;
    if (i < JP) {
        float4 w = make_float4(0.f, 0.f, 0.f, 0.f);
        float lw = 0.f;
        if (i < HIDDEN) {
            w.x = W_w[0 * HIDDEN + i]; w.y = W_w[1 * HIDDEN + i];
            w.z = W_w[2 * HIDDEN + i]; w.w = W_w[3 * HIDDEN + i];
            lw = lin_w[i];
        }
        g_W4[i] = w; g_L[i] = lw;
    }
}

// ---------- main ----------
// 512 threads = 2 groups x 256. Group: 4 batches, k in 4 quarters.
// Group thread = q*64 + j (q = quarter, j = hidden unit). Warp w = q*2 + (j>=32).
__global__ void __launch_bounds__(THREADS, 1)
lstm_main(const float* __restrict__ x, const float* __restrict__ lin_b,
          float* __restrict__ out) {
    // h duplicated: h_shd[g][buf][row][b] = (h,h) for batch b  (32B per row)
    __shared__ __align__(16) ull        h_shd[2][2][KROWS][4];
    __shared__ __align__(16) ulonglong2 psum[2][4][4][JP];   // [grp][q][batch][j] = (a_if, a_go)
    __shared__ float redp[2][8];                             // [grp][warp-in-group]

    const int tid  = threadIdx.x;
    const int g    = tid >> 8;
    const int gtid = tid & 255;
    const int q    = gtid >> 6;        // k-quarter AND phase-B batch
    const int j    = gtid & 63;        // hidden unit
    const int lane = tid & 31;
    const int wgrp = gtid >> 5;        // warp within group (0..7) = q*2 + jhalf
    const int b0   = blockIdx.x * 8 + g * 4;

    // Register-resident U rows q*13 .. q*13+12, gate-packed pairs (52 regs)
    ull u_if[KQ], u_go[KQ];
#pragma unroll
    for (int kk = 0; kk < KQ; kk++) {
        float4 u = g_U4[(q * KQ + kk) * JP + j];
        u_if[kk] = pk2(u.x, u.y);
        u_go[kk] = pk2(u.z, u.w);
    }
    const float4 wv  = g_W4[j];
    const float  lw  = g_L[j];
    const float  lbv = lin_b[0];

    // init h: zeros; bias row 51 = (1,1) in BOTH buffers (never rewritten)
    for (int i = tid; i < 2 * 2 * KROWS * 4; i += THREADS) {
        int row = (i >> 2) % KROWS;
        ((ull*)h_shd)[i] = (row == HIDDEN) ? pk2(1.f, 1.f) : 0ULL;
    }
    __syncthreads();

    float c  = 0.f;                          // cell state for (unit j, batch q)
    float xq = x[(b0 + q) * L_SEQ + 0];      // x for my batch, t=0

    for (int t = 0; t < L_SEQ; ++t) {
        const int rb = t & 1, wb = rb ^ 1;

        // ---- phase A: my 13 k-rows, all 4 batches, zero-mov inner loop ----
        ull a_if0 = 0ULL, a_go0 = 0ULL, a_if1 = 0ULL, a_go1 = 0ULL;
        ull a_if2 = 0ULL, a_go2 = 0ULL, a_if3 = 0ULL, a_go3 = 0ULL;
        const ulonglong2* hr = (const ulonglong2*)&h_shd[g][rb][q * KQ][0];
#pragma unroll
        for (int kk = 0; kk < KQ; kk++) {
            ulonglong2 h01 = hr[kk * 2 + 0];   // (h,h)b0, (h,h)b1  — broadcast LDS.128
            ulonglong2 h23 = hr[kk * 2 + 1];   // (h,h)b2, (h,h)b3
            a_if0 = f2fma(h01.x, u_if[kk], a_if0); a_go0 = f2fma(h01.x, u_go[kk], a_go0);
            a_if1 = f2fma(h01.y, u_if[kk], a_if1); a_go1 = f2fma(h01.y, u_go[kk], a_go1);
            a_if2 = f2fma(h23.x, u_if[kk], a_if2); a_go2 = f2fma(h23.x, u_go[kk], a_go2);
            a_if3 = f2fma(h23.y, u_if[kk], a_if3); a_go3 = f2fma(h23.y, u_go[kk], a_go3);
        }
        { ulonglong2 v; v.x = a_if0; v.y = a_go0; psum[g][q][0][j] = v; }
        { ulonglong2 v; v.x = a_if1; v.y = a_go1; psum[g][q][1][j] = v; }
        { ulonglong2 v; v.x = a_if2; v.y = a_go2; psum[g][q][2][j] = v; }
        { ulonglong2 v; v.x = a_if3; v.y = a_go3; psum[g][q][3][j] = v; }

        // prefetch next x (converged LDG, hidden under barrier/phase B)
        float xn = x[(b0 + q) * L_SEQ + ((t + 1 < L_SEQ) ? t + 1 : t)];

        group_bar(g + 1);

        // ---- phase B: combine 4 quarters for (j, batch q), update c/h ----
        ulonglong2 p0 = psum[g][0][q][j];
        ulonglong2 p1 = psum[g][1][q][j];
        ulonglong2 p2 = psum[g][2][q][j];
        ulonglong2 p3 = psum[g][3][q][j];
        ull s_if = f2add(f2add(p0.x, p1.x), f2add(p2.x, p3.x));
        ull s_go = f2add(f2add(p0.y, p1.y), f2add(p2.y, p3.y));
        float gi, gf, gg, go;
        up2(gi, gf, s_if);
        up2(gg, go, s_go);
        gi = fmaf(xq, wv.x, gi);
        gf = fmaf(xq, wv.y, gf);
        gg = fmaf(xq, wv.z, gg);
        go = fmaf(xq, wv.w, go);
        c = fmaf(gf, c, gi * gg);               // faithful: no sigmoids
        float h = go * fast_tanh(c);
        if (j < HIDDEN) h_shd[g][wb][j][q] = pk2(h, h);

        float prod = h * lw;
        prod += __shfl_xor_sync(0xffffffffu, prod, 1);
        prod += __shfl_xor_sync(0xffffffffu, prod, 2);
        prod += __shfl_xor_sync(0xffffffffu, prod, 4);
        prod += __shfl_xor_sync(0xffffffffu, prod, 8);
        prod += __shfl_xor_sync(0xffffffffu, prod, 16);
        if (lane == 0) redp[g][wgrp] = prod;

        xq = xn;
        group_bar(g + 1);

        // ---- output for step t (4 threads per group; overlaps next phase A) ----
        if (gtid < 4) {
            int b = gtid;
            out[(b0 + b) * L_SEQ + t] = redp[g][2 * b] + redp[g][2 * b + 1] + lbv;
        }
    }
}

extern "C" void kernel_launch(void* const* d_in, const int* in_sizes, int n_in,
                              void* d_out, int out_size) {
    (void)in_sizes; (void)n_in; (void)out_size;
    const float* x     = (const float*)d_in[0];
    const float* W_w   = (const float*)d_in[1];
    const float* W_b   = (const float*)d_in[2];
    const float* U_w   = (const float*)d_in[3];
    const float* U_b   = (const float*)d_in[4];
    const float* lin_w = (const float*)d_in[5];
    const float* lin_b = (const float*)d_in[6];
    // d_in[7] = future (static 0) — ignored.

    prep_kernel<<<26, 128>>>(W_w, W_b, U_w, U_b, lin_w);
    lstm_main<<<NBLK, THREADS>>>(x, lin_b, (float*)d_out);
}